// round 4
// baseline (speedup 1.0000x reference)
#include <cuda_runtime.h>

// Problem constants (match reference)
#define NB     4
#define HH     512
#define WW     512
#define KK     4
#define SIGMA  1e-4f
#define GAMMA  1e-4f
#define EPSV   1e-10f
#define ZNEAR  1.0f
#define ZFAR   100.0f

#define NPIX (NB * HH * WW)   // 1,048,576

__global__ __launch_bounds__(256) void normal_shader_kernel(
    const float* __restrict__ vertex_normals,   // [V,3]
    const float* __restrict__ bary,             // [N,H,W,K,3]
    const float* __restrict__ dists,            // [N,H,W,K]
    const float* __restrict__ zbuf,             // [N,H,W,K]
    const int*   __restrict__ faces,            // [F,3]
    const int*   __restrict__ pix_to_face,      // [N,H,W,K]
    float*       __restrict__ out)              // [N,H,W,3]
{
    int p = blockIdx.x * blockDim.x + threadIdx.x;
    if (p >= NPIX) return;

    // ---- coalesced vector loads of per-fragment data ----
    const int4   ptf = __ldg((const int4*)(pix_to_face) + p);
    const float4 dd  = __ldg((const float4*)(dists) + p);
    const float4 zz  = __ldg((const float4*)(zbuf) + p);
    // bary: 12 floats per pixel, 48B aligned -> 3 float4 loads
    const float4* bb = (const float4*)(bary + (size_t)p * 12);
    const float4 b0 = __ldg(bb + 0);
    const float4 b1 = __ldg(bb + 1);
    const float4 b2 = __ldg(bb + 2);

    int   face[KK] = {ptf.x, ptf.y, ptf.z, ptf.w};
    float dk[KK]   = {dd.x, dd.y, dd.z, dd.w};
    float zk[KK]   = {zz.x, zz.y, zz.z, zz.w};
    // bary per fragment k: (bw[k][0..2])
    float bw[KK][3] = {
        {b0.x, b0.y, b0.z},
        {b0.w, b1.x, b1.y},
        {b1.z, b1.w, b2.x},
        {b2.y, b2.z, b2.w}
    };

    // ---- interpolated normals (gather), coverage prob, z_inv ----
    float nrm[KK][3];
    float prob[KK];
    float zinv[KK];
    float zmax = EPSV;

    #pragma unroll
    for (int k = 0; k < KK; k++) {
        const bool valid = face[k] >= 0;
        float nx = 0.f, ny = 0.f, nz = 0.f;
        if (valid) {
            const int fi = face[k];
            const int v0 = __ldg(faces + 3 * fi + 0);
            const int v1 = __ldg(faces + 3 * fi + 1);
            const int v2 = __ldg(faces + 3 * fi + 2);
            const float w0 = bw[k][0], w1 = bw[k][1], w2 = bw[k][2];
            const float* n0 = vertex_normals + 3 * v0;
            const float* n1 = vertex_normals + 3 * v1;
            const float* n2 = vertex_normals + 3 * v2;
            nx = w0 * __ldg(n0 + 0) + w1 * __ldg(n1 + 0) + w2 * __ldg(n2 + 0);
            ny = w0 * __ldg(n0 + 1) + w1 * __ldg(n1 + 1) + w2 * __ldg(n2 + 1);
            nz = w0 * __ldg(n0 + 2) + w1 * __ldg(n1 + 2) + w2 * __ldg(n2 + 2);
        }
        nrm[k][0] = nx; nrm[k][1] = ny; nrm[k][2] = nz;

        // prob = sigmoid(-d/SIGMA) * mask   (exact: 1/(1+exp(d/SIGMA)))
        float pr = 0.f;
        float zi = 0.f;
        if (valid) {
            pr = 1.0f / (1.0f + expf(dk[k] / SIGMA));
            zi = (ZFAR - zk[k]) / (ZFAR - ZNEAR);
        }
        prob[k] = pr;
        zinv[k] = zi;
        zmax = fmaxf(zmax, zi);
    }

    // ---- softmax blend ----
    float accx = 0.f, accy = 0.f, accz = 0.f, wsum = 0.f;
    #pragma unroll
    for (int k = 0; k < KK; k++) {
        const float w = prob[k] * expf((zinv[k] - zmax) / GAMMA);
        wsum += w;
        accx += w * nrm[k][0];
        accy += w * nrm[k][1];
        accz += w * nrm[k][2];
    }
    const float delta = fmaxf(expf((EPSV - zmax) / GAMMA), EPSV);
    const float denom = wsum + delta;

    // bg = (1,1,1)
    float rx = (accx + delta) / denom;
    float ry = (accy + delta) / denom;
    float rz = (accz + delta) / denom;

    const float nn = fmaxf(sqrtf(rx * rx + ry * ry + rz * rz), 1e-12f);
    rx /= nn; ry /= nn; rz /= nn;

    float* o = out + (size_t)p * 3;
    o[0] = rx; o[1] = ry; o[2] = rz;
}

extern "C" void kernel_launch(void* const* d_in, const int* in_sizes, int n_in,
                              void* d_out, int out_size)
{
    // metadata order: verts, vertex_normals, bary_coords, dists, zbuf, faces, pix_to_face
    // (verts is unused by the reference computation)
    const float* vertex_normals = (const float*)d_in[1];
    const float* bary           = (const float*)d_in[2];
    const float* dists          = (const float*)d_in[3];
    const float* zbuf           = (const float*)d_in[4];
    const int*   faces          = (const int*)d_in[5];
    const int*   pix_to_face    = (const int*)d_in[6];
    float*       out            = (float*)d_out;

    const int threads = 256;
    const int blocks  = (NPIX + threads - 1) / threads;
    normal_shader_kernel<<<blocks, threads>>>(
        vertex_normals, bary, dists, zbuf, faces, pix_to_face, out);
}

// round 5
// speedup vs baseline: 1.6085x; 1.6085x over previous
#include <cuda_runtime.h>

// Problem constants (match reference)
#define NB     4
#define HH     512
#define WW     512
#define KK     4
#define FMAX   200000
#define SIGMA  1e-4f
#define GAMMA  1e-4f
#define EPSV   1e-10f
#define ZNEAR  1.0f
#define ZFAR   100.0f

#define NPIX (NB * HH * WW)   // 1,048,576

// Packed per-face vertex-normal records: 4 float4 per face (64B stride, only
// first 3 used). 64B-aligned stride => a 48B record read touches exactly two
// 32B sectors. 12.8 MB — fits in L2.
__device__ float4 g_facerec[FMAX * 4];

__global__ __launch_bounds__(256) void build_face_records(
    const float* __restrict__ vertex_normals,   // [V,3]
    const int*   __restrict__ faces,            // [F,3]
    int F)
{
    int f = blockIdx.x * blockDim.x + threadIdx.x;
    if (f >= F) return;
    const int v0 = __ldg(faces + 3 * f + 0);
    const int v1 = __ldg(faces + 3 * f + 1);
    const int v2 = __ldg(faces + 3 * f + 2);
    const float* n0 = vertex_normals + 3 * v0;
    const float* n1 = vertex_normals + 3 * v1;
    const float* n2 = vertex_normals + 3 * v2;
    float4* rec = g_facerec + (size_t)f * 4;
    rec[0] = make_float4(__ldg(n0 + 0), __ldg(n0 + 1), __ldg(n0 + 2), 0.f);
    rec[1] = make_float4(__ldg(n1 + 0), __ldg(n1 + 1), __ldg(n1 + 2), 0.f);
    rec[2] = make_float4(__ldg(n2 + 0), __ldg(n2 + 1), __ldg(n2 + 2), 0.f);
}

__global__ __launch_bounds__(256) void normal_shader_kernel(
    const float* __restrict__ bary,             // [N,H,W,K,3]
    const float* __restrict__ dists,            // [N,H,W,K]
    const float* __restrict__ zbuf,             // [N,H,W,K]
    const int*   __restrict__ pix_to_face,      // [N,H,W,K]
    float*       __restrict__ out)              // [N,H,W,3]
{
    int p = blockIdx.x * blockDim.x + threadIdx.x;
    if (p >= NPIX) return;

    // ---- coalesced vector loads of per-fragment data ----
    const int4   ptf = __ldg((const int4*)(pix_to_face) + p);
    const float4 dd  = __ldg((const float4*)(dists) + p);
    const float4 zz  = __ldg((const float4*)(zbuf) + p);
    const float4* bb = (const float4*)(bary + (size_t)p * 12);
    const float4 b0 = __ldg(bb + 0);
    const float4 b1 = __ldg(bb + 1);
    const float4 b2 = __ldg(bb + 2);

    int   face[KK] = {ptf.x, ptf.y, ptf.z, ptf.w};
    float dk[KK]   = {dd.x, dd.y, dd.z, dd.w};
    float zk[KK]   = {zz.x, zz.y, zz.z, zz.w};
    float bw[KK][3] = {
        {b0.x, b0.y, b0.z},
        {b0.w, b1.x, b1.y},
        {b1.z, b1.w, b2.x},
        {b2.y, b2.z, b2.w}
    };

    // ---- gather packed face records, interpolate normals; prob & z_inv ----
    float nrm[KK][3];
    float prob[KK];
    float zinv[KK];
    float zmax = EPSV;

    #pragma unroll
    for (int k = 0; k < KK; k++) {
        const bool valid = face[k] >= 0;
        float nx = 0.f, ny = 0.f, nz = 0.f;
        if (valid) {
            const float4* rec = g_facerec + (size_t)face[k] * 4;
            const float4 n0 = __ldg(rec + 0);
            const float4 n1 = __ldg(rec + 1);
            const float4 n2 = __ldg(rec + 2);
            const float w0 = bw[k][0], w1 = bw[k][1], w2 = bw[k][2];
            nx = w0 * n0.x + w1 * n1.x + w2 * n2.x;
            ny = w0 * n0.y + w1 * n1.y + w2 * n2.y;
            nz = w0 * n0.z + w1 * n1.z + w2 * n2.z;
        }
        nrm[k][0] = nx; nrm[k][1] = ny; nrm[k][2] = nz;

        float pr = 0.f;
        float zi = 0.f;
        if (valid) {
            // sigmoid(-d/SIGMA) = 1/(1+exp(d/SIGMA)) — exact IEEE ops to
            // match the JAX fp32 rounding (GAMMA=1e-4 amplifies ulps).
            pr = 1.0f / (1.0f + expf(dk[k] / SIGMA));
            zi = (ZFAR - zk[k]) / (ZFAR - ZNEAR);
        }
        prob[k] = pr;
        zinv[k] = zi;
        zmax = fmaxf(zmax, zi);
    }

    // ---- softmax blend ----
    float accx = 0.f, accy = 0.f, accz = 0.f, wsum = 0.f;
    #pragma unroll
    for (int k = 0; k < KK; k++) {
        const float w = prob[k] * expf((zinv[k] - zmax) / GAMMA);
        wsum += w;
        accx += w * nrm[k][0];
        accy += w * nrm[k][1];
        accz += w * nrm[k][2];
    }
    const float delta = fmaxf(expf((EPSV - zmax) / GAMMA), EPSV);
    const float denom = wsum + delta;

    // bg = (1,1,1)
    float rx = (accx + delta) / denom;
    float ry = (accy + delta) / denom;
    float rz = (accz + delta) / denom;

    const float nn = fmaxf(sqrtf(rx * rx + ry * ry + rz * rz), 1e-12f);
    rx /= nn; ry /= nn; rz /= nn;

    float* o = out + (size_t)p * 3;
    o[0] = rx; o[1] = ry; o[2] = rz;
}

extern "C" void kernel_launch(void* const* d_in, const int* in_sizes, int n_in,
                              void* d_out, int out_size)
{
    // metadata order: verts, vertex_normals, bary_coords, dists, zbuf, faces, pix_to_face
    const float* vertex_normals = (const float*)d_in[1];
    const float* bary           = (const float*)d_in[2];
    const float* dists          = (const float*)d_in[3];
    const float* zbuf           = (const float*)d_in[4];
    const int*   faces          = (const int*)d_in[5];
    const int*   pix_to_face    = (const int*)d_in[6];
    float*       out            = (float*)d_out;

    const int F = in_sizes[5] / 3;   // 200000

    const int threads = 256;
    build_face_records<<<(F + threads - 1) / threads, threads>>>(
        vertex_normals, faces, F);

    normal_shader_kernel<<<(NPIX + threads - 1) / threads, threads>>>(
        bary, dists, zbuf, pix_to_face, out);
}

// round 6
// speedup vs baseline: 1.9739x; 1.2272x over previous
#include <cuda_runtime.h>

// Problem constants (match reference)
#define NB     4
#define HH     512
#define WW     512
#define KK     4
#define FMAX   200000
#define SIGMA  1e-4f
#define GAMMA  1e-4f
#define EPSV   1e-10f
#define ZNEAR  1.0f
#define ZFAR   100.0f

#define NPIX (NB * HH * WW)   // 1,048,576

// Packed per-face record: 32 bytes = ONE 32B L2 sector.
//   a = (n0x, n0y, n0z, n1x), b = (n1y, n1z, n2x, n2y)
// The 32 bits of n2z are hidden in the low 4 mantissa bits of the 8 stored
// floats (nibble i in component i, order a.x..a.w, b.x..b.w). Decode is
// bit-exact for n2z; carriers are perturbed by <=15 ulp (~9e-7 rel).
struct __align__(32) FaceRec { float4 a, b; };
__device__ FaceRec g_facerec[FMAX];

__device__ __forceinline__ unsigned fb(float v) { return __float_as_uint(v); }

__global__ __launch_bounds__(256) void build_face_records(
    const float* __restrict__ vertex_normals,   // [V,3]
    const int*   __restrict__ faces,            // [F,3]
    int F)
{
    int f = blockIdx.x * blockDim.x + threadIdx.x;
    if (f >= F) return;
    const int v0 = __ldg(faces + 3 * f + 0);
    const int v1 = __ldg(faces + 3 * f + 1);
    const int v2 = __ldg(faces + 3 * f + 2);

    float c[8];
    c[0] = __ldg(vertex_normals + 3 * v0 + 0);
    c[1] = __ldg(vertex_normals + 3 * v0 + 1);
    c[2] = __ldg(vertex_normals + 3 * v0 + 2);
    c[3] = __ldg(vertex_normals + 3 * v1 + 0);
    c[4] = __ldg(vertex_normals + 3 * v1 + 1);
    c[5] = __ldg(vertex_normals + 3 * v1 + 2);
    c[6] = __ldg(vertex_normals + 3 * v2 + 0);
    c[7] = __ldg(vertex_normals + 3 * v2 + 1);
    const unsigned u = __float_as_uint(__ldg(vertex_normals + 3 * v2 + 2));

    #pragma unroll
    for (int i = 0; i < 8; i++) {
        unsigned bits = (__float_as_uint(c[i]) & ~0xFu) | ((u >> (4 * i)) & 0xFu);
        c[i] = __uint_as_float(bits);
    }

    FaceRec r;
    r.a = make_float4(c[0], c[1], c[2], c[3]);
    r.b = make_float4(c[4], c[5], c[6], c[7]);
    g_facerec[f] = r;
}

__global__ __launch_bounds__(256) void normal_shader_kernel(
    const float* __restrict__ bary,             // [N,H,W,K,3]
    const float* __restrict__ dists,            // [N,H,W,K]
    const float* __restrict__ zbuf,             // [N,H,W,K]
    const int*   __restrict__ pix_to_face,      // [N,H,W,K]
    float*       __restrict__ out)              // [N,H,W,3]
{
    int p = blockIdx.x * blockDim.x + threadIdx.x;
    if (p >= NPIX) return;

    // ---- coalesced vector loads of per-fragment data ----
    const int4   ptf = __ldg((const int4*)(pix_to_face) + p);
    const float4 dd  = __ldg((const float4*)(dists) + p);
    const float4 zz  = __ldg((const float4*)(zbuf) + p);
    const float4* bb = (const float4*)(bary + (size_t)p * 12);
    const float4 b0 = __ldg(bb + 0);
    const float4 b1 = __ldg(bb + 1);
    const float4 b2 = __ldg(bb + 2);

    int   face[KK] = {ptf.x, ptf.y, ptf.z, ptf.w};
    float dk[KK]   = {dd.x, dd.y, dd.z, dd.w};
    float zk[KK]   = {zz.x, zz.y, zz.z, zz.w};
    float bw[KK][3] = {
        {b0.x, b0.y, b0.z},
        {b0.w, b1.x, b1.y},
        {b1.z, b1.w, b2.x},
        {b2.y, b2.z, b2.w}
    };

    float nrm[KK][3];
    float prob[KK];
    float zinv[KK];
    float zmax = EPSV;

    #pragma unroll
    for (int k = 0; k < KK; k++) {
        const bool valid = face[k] >= 0;
        float nx = 0.f, ny = 0.f, nz = 0.f;
        if (valid) {
            const FaceRec* rp = g_facerec + face[k];
            const float4 a = __ldg(&rp->a);
            const float4 b = __ldg(&rp->b);
            // reconstruct n2z from the 8 stolen nibbles (bit-exact)
            unsigned u =  (fb(a.x) & 0xFu)
                       | ((fb(a.y) & 0xFu) << 4)
                       | ((fb(a.z) & 0xFu) << 8)
                       | ((fb(a.w) & 0xFu) << 12)
                       | ((fb(b.x) & 0xFu) << 16)
                       | ((fb(b.y) & 0xFu) << 20)
                       | ((fb(b.z) & 0xFu) << 24)
                       | ((fb(b.w) & 0xFu) << 28);
            const float n2z = __uint_as_float(u);
            const float w0 = bw[k][0], w1 = bw[k][1], w2 = bw[k][2];
            nx = w0 * a.x + w1 * a.w + w2 * b.z;
            ny = w0 * a.y + w1 * b.x + w2 * b.w;
            nz = w0 * a.z + w1 * b.y + w2 * n2z;
        }
        nrm[k][0] = nx; nrm[k][1] = ny; nrm[k][2] = nz;

        float pr = 0.f;
        float zi = 0.f;
        if (valid) {
            // sigmoid(-d/SIGMA) = 1/(1+exp(d/SIGMA)) — exact IEEE ops to
            // match JAX fp32 rounding (GAMMA=1e-4 amplifies ulps).
            pr = 1.0f / (1.0f + expf(dk[k] / SIGMA));
            zi = (ZFAR - zk[k]) / (ZFAR - ZNEAR);
        }
        prob[k] = pr;
        zinv[k] = zi;
        zmax = fmaxf(zmax, zi);
    }

    // ---- softmax blend ----
    float accx = 0.f, accy = 0.f, accz = 0.f, wsum = 0.f;
    #pragma unroll
    for (int k = 0; k < KK; k++) {
        const float w = prob[k] * expf((zinv[k] - zmax) / GAMMA);
        wsum += w;
        accx += w * nrm[k][0];
        accy += w * nrm[k][1];
        accz += w * nrm[k][2];
    }
    const float delta = fmaxf(expf((EPSV - zmax) / GAMMA), EPSV);
    const float denom = wsum + delta;

    // bg = (1,1,1)
    float rx = (accx + delta) / denom;
    float ry = (accy + delta) / denom;
    float rz = (accz + delta) / denom;

    const float nn = fmaxf(sqrtf(rx * rx + ry * ry + rz * rz), 1e-12f);
    rx /= nn; ry /= nn; rz /= nn;

    float* o = out + (size_t)p * 3;
    o[0] = rx; o[1] = ry; o[2] = rz;
}

extern "C" void kernel_launch(void* const* d_in, const int* in_sizes, int n_in,
                              void* d_out, int out_size)
{
    // metadata order: verts, vertex_normals, bary_coords, dists, zbuf, faces, pix_to_face
    const float* vertex_normals = (const float*)d_in[1];
    const float* bary           = (const float*)d_in[2];
    const float* dists          = (const float*)d_in[3];
    const float* zbuf           = (const float*)d_in[4];
    const int*   faces          = (const int*)d_in[5];
    const int*   pix_to_face    = (const int*)d_in[6];
    float*       out            = (float*)d_out;

    const int F = in_sizes[5] / 3;   // 200000

    const int threads = 256;
    build_face_records<<<(F + threads - 1) / threads, threads>>>(
        vertex_normals, faces, F);

    normal_shader_kernel<<<(NPIX + threads - 1) / threads, threads>>>(
        bary, dists, zbuf, pix_to_face, out);
}

// round 7
// speedup vs baseline: 2.3607x; 1.1959x over previous
#include <cuda_runtime.h>

// Problem constants (match reference)
#define NB     4
#define HH     512
#define WW     512
#define KK     4
#define FMAX   200000
#define VMAX   100000
#define SIGMA  1e-4f
#define GAMMA  1e-4f
#define EPSV   1e-10f
#define ZNEAR  1.0f
#define ZFAR   100.0f

#define NPIX (NB * HH * WW)   // 1,048,576

// 1/SIGMA and 1/GAMMA are exactly representable (10000.0f) -> mul == div here.
#define INV_SG 10000.0f

// Padded vertex normals: one float4 (= one aligned 16B chunk) per vertex.
__device__ float4 g_vn4[VMAX];

// Packed per-face record: 32 bytes = ONE 32B L2 sector, loaded with a single
// 256-bit LDG.  a = (n0x,n0y,n0z,n1x), b = (n1y,n1z,n2x,n2y); the 32 bits of
// n2z are hidden in the low 4 mantissa bits of the 8 stored floats (nibble i
// in component i). n2z decode is bit-exact; carriers perturbed <=15 ulp.
struct __align__(32) FaceRec { float4 a, b; };
__device__ FaceRec g_facerec[FMAX];

__device__ __forceinline__ unsigned fb(float v) { return __float_as_uint(v); }

// 256-bit global load (sm_100+): one instruction, one sector per lane.
__device__ __forceinline__ void ldg256(const FaceRec* p, float4& a, float4& b) {
    asm volatile("ld.global.v8.f32 {%0,%1,%2,%3,%4,%5,%6,%7}, [%8];"
                 : "=f"(a.x), "=f"(a.y), "=f"(a.z), "=f"(a.w),
                   "=f"(b.x), "=f"(b.y), "=f"(b.z), "=f"(b.w)
                 : "l"(p));
}

__global__ __launch_bounds__(256) void pad_vertex_normals(
    const float* __restrict__ vertex_normals, int Vn)
{
    int v = blockIdx.x * blockDim.x + threadIdx.x;
    if (v >= Vn) return;
    g_vn4[v] = make_float4(__ldg(vertex_normals + 3 * v + 0),
                           __ldg(vertex_normals + 3 * v + 1),
                           __ldg(vertex_normals + 3 * v + 2), 0.f);
}

__global__ __launch_bounds__(256) void build_face_records(
    const int* __restrict__ faces, int F)
{
    int f = blockIdx.x * blockDim.x + threadIdx.x;
    if (f >= F) return;
    const int v0 = __ldg(faces + 3 * f + 0);
    const int v1 = __ldg(faces + 3 * f + 1);
    const int v2 = __ldg(faces + 3 * f + 2);
    const float4 n0 = g_vn4[v0];
    const float4 n1 = g_vn4[v1];
    const float4 n2 = g_vn4[v2];

    float c[8] = {n0.x, n0.y, n0.z, n1.x, n1.y, n1.z, n2.x, n2.y};
    const unsigned u = __float_as_uint(n2.z);
    #pragma unroll
    for (int i = 0; i < 8; i++) {
        unsigned bits = (__float_as_uint(c[i]) & ~0xFu) | ((u >> (4 * i)) & 0xFu);
        c[i] = __uint_as_float(bits);
    }

    FaceRec r;
    r.a = make_float4(c[0], c[1], c[2], c[3]);
    r.b = make_float4(c[4], c[5], c[6], c[7]);
    g_facerec[f] = r;
}

__global__ __launch_bounds__(256) void normal_shader_kernel(
    const float* __restrict__ bary,             // [N,H,W,K,3]
    const float* __restrict__ dists,            // [N,H,W,K]
    const float* __restrict__ zbuf,             // [N,H,W,K]
    const int*   __restrict__ pix_to_face,      // [N,H,W,K]
    float*       __restrict__ out)              // [N,H,W,3]
{
    int p = blockIdx.x * blockDim.x + threadIdx.x;
    if (p >= NPIX) return;

    // ---- coalesced vector loads of per-fragment data ----
    const int4   ptf = __ldg((const int4*)(pix_to_face) + p);
    const float4 dd  = __ldg((const float4*)(dists) + p);
    const float4 zz  = __ldg((const float4*)(zbuf) + p);
    const float4* bb = (const float4*)(bary + (size_t)p * 12);
    const float4 b0 = __ldg(bb + 0);
    const float4 b1 = __ldg(bb + 1);
    const float4 b2 = __ldg(bb + 2);

    int   face[KK] = {ptf.x, ptf.y, ptf.z, ptf.w};
    float dk[KK]   = {dd.x, dd.y, dd.z, dd.w};
    float zk[KK]   = {zz.x, zz.y, zz.z, zz.w};
    float bw[KK][3] = {
        {b0.x, b0.y, b0.z},
        {b0.w, b1.x, b1.y},
        {b1.z, b1.w, b2.x},
        {b2.y, b2.z, b2.w}
    };

    float nrm[KK][3];
    float prob[KK];
    float zinv[KK];
    float zmax = EPSV;

    #pragma unroll
    for (int k = 0; k < KK; k++) {
        const bool valid = face[k] >= 0;
        float nx = 0.f, ny = 0.f, nz = 0.f;
        if (valid) {
            float4 a, b;
            ldg256(g_facerec + face[k], a, b);
            // reconstruct n2z from the 8 stolen nibbles (bit-exact)
            unsigned u =  (fb(a.x) & 0xFu)
                       | ((fb(a.y) & 0xFu) << 4)
                       | ((fb(a.z) & 0xFu) << 8)
                       | ((fb(a.w) & 0xFu) << 12)
                       | ((fb(b.x) & 0xFu) << 16)
                       | ((fb(b.y) & 0xFu) << 20)
                       | ((fb(b.z) & 0xFu) << 24)
                       | ((fb(b.w) & 0xFu) << 28);
            const float n2z = __uint_as_float(u);
            const float w0 = bw[k][0], w1 = bw[k][1], w2 = bw[k][2];
            nx = w0 * a.x + w1 * a.w + w2 * b.z;
            ny = w0 * a.y + w1 * b.x + w2 * b.w;
            nz = w0 * a.z + w1 * b.y + w2 * n2z;
        }
        nrm[k][0] = nx; nrm[k][1] = ny; nrm[k][2] = nz;

        float pr = 0.f;
        float zi = 0.f;
        if (valid) {
            // sigmoid(-d/SIGMA): arg ~ N(0,1), __expf err ~1e-6 here.
            pr = __fdividef(1.0f, 1.0f + __expf(dk[k] * INV_SG));
            // zi MUST use the exact IEEE div (1 ulp here amplifies ~1e4x
            // through the softmax exponent).
            zi = (ZFAR - zk[k]) / (ZFAR - ZNEAR);
        }
        prob[k] = pr;
        zinv[k] = zi;
        zmax = fmaxf(zmax, zi);
    }

    // ---- softmax blend ----
    // exp arg error here is relative to the arg (mul by exact 1e4f), so
    // meaningful weights (|arg|<~35) carry <=5e-6 rel error with __expf.
    float accx = 0.f, accy = 0.f, accz = 0.f, wsum = 0.f;
    #pragma unroll
    for (int k = 0; k < KK; k++) {
        const float w = prob[k] * __expf((zinv[k] - zmax) * INV_SG);
        wsum += w;
        accx += w * nrm[k][0];
        accy += w * nrm[k][1];
        accz += w * nrm[k][2];
    }
    const float delta = fmaxf(__expf((EPSV - zmax) * INV_SG), EPSV);
    const float rdenom = __fdividef(1.0f, wsum + delta);

    // bg = (1,1,1)
    float rx = (accx + delta) * rdenom;
    float ry = (accy + delta) * rdenom;
    float rz = (accz + delta) * rdenom;

    const float n2 = rx * rx + ry * ry + rz * rz;
    const float inv = (n2 > 1e-24f) ? rsqrtf(n2) : 1e12f;
    rx *= inv; ry *= inv; rz *= inv;

    float* o = out + (size_t)p * 3;
    o[0] = rx; o[1] = ry; o[2] = rz;
}

extern "C" void kernel_launch(void* const* d_in, const int* in_sizes, int n_in,
                              void* d_out, int out_size)
{
    // metadata order: verts, vertex_normals, bary_coords, dists, zbuf, faces, pix_to_face
    const float* vertex_normals = (const float*)d_in[1];
    const float* bary           = (const float*)d_in[2];
    const float* dists          = (const float*)d_in[3];
    const float* zbuf           = (const float*)d_in[4];
    const int*   faces          = (const int*)d_in[5];
    const int*   pix_to_face    = (const int*)d_in[6];
    float*       out            = (float*)d_out;

    const int Vn = in_sizes[1] / 3;  // 100000
    const int F  = in_sizes[5] / 3;  // 200000

    const int threads = 256;
    pad_vertex_normals<<<(Vn + threads - 1) / threads, threads>>>(vertex_normals, Vn);
    build_face_records<<<(F + threads - 1) / threads, threads>>>(faces, F);
    normal_shader_kernel<<<(NPIX + threads - 1) / threads, threads>>>(
        bary, dists, zbuf, pix_to_face, out);
}

// round 8
// speedup vs baseline: 2.4565x; 1.0406x over previous
#include <cuda_runtime.h>

// Problem constants (match reference)
#define NB     4
#define HH     512
#define WW     512
#define KK     4
#define FMAX   200000
#define SIGMA  1e-4f
#define GAMMA  1e-4f
#define EPSV   1e-10f
#define ZNEAR  1.0f
#define ZFAR   100.0f

#define NPIX (NB * HH * WW)   // 1,048,576 == 4096 * 256 exactly

// 1/SIGMA and 1/GAMMA are exactly representable (10000.0f) -> mul == div.
#define INV_SG 10000.0f

// Packed per-face record: 32 bytes = ONE 32B L2 sector, loaded with a single
// 256-bit LDG.  a = (n0x,n0y,n0z,n1x), b = (n1y,n1z,n2x,n2y); the 32 bits of
// n2z are hidden in the low 4 mantissa bits of the 8 stored floats (nibble i
// in component i). n2z decode is bit-exact; carriers perturbed <=15 ulp.
struct __align__(32) FaceRec { float4 a, b; };
__device__ FaceRec g_facerec[FMAX];

__device__ __forceinline__ unsigned fb(float v) { return __float_as_uint(v); }

// 256-bit global load (sm_100+): one instruction, one sector per lane.
__device__ __forceinline__ void ldg256(const FaceRec* p, float4& a, float4& b) {
    asm volatile("ld.global.v8.f32 {%0,%1,%2,%3,%4,%5,%6,%7}, [%8];"
                 : "=f"(a.x), "=f"(a.y), "=f"(a.z), "=f"(a.w),
                   "=f"(b.x), "=f"(b.y), "=f"(b.z), "=f"(b.w)
                 : "l"(p));
}

// Branchless gather of a 12B float3 at float-offset 3v using TWO aligned
// float2 loads (off = 3v - (v&1) is always even; both halves 8B-aligned and
// in-bounds for V=100000).
__device__ __forceinline__ float3 load_vn(const float* __restrict__ vn, int v) {
    const int off = 3 * v - (v & 1);
    const float2 A = __ldg((const float2*)vn + (off >> 1));
    const float2 B = __ldg((const float2*)vn + (off >> 1) + 1);
    const bool odd = (v & 1);
    float3 r;
    r.x = odd ? A.y : A.x;
    r.y = odd ? B.x : A.y;
    r.z = odd ? B.y : B.x;
    return r;
}

__global__ __launch_bounds__(256) void build_face_records(
    const float* __restrict__ vertex_normals,   // [V,3]
    const int*   __restrict__ faces,            // [F,3]
    int F)
{
    int f = blockIdx.x * blockDim.x + threadIdx.x;
    if (f >= F) return;
    const int v0 = __ldg(faces + 3 * f + 0);
    const int v1 = __ldg(faces + 3 * f + 1);
    const int v2 = __ldg(faces + 3 * f + 2);
    const float3 n0 = load_vn(vertex_normals, v0);
    const float3 n1 = load_vn(vertex_normals, v1);
    const float3 n2 = load_vn(vertex_normals, v2);

    float c[8] = {n0.x, n0.y, n0.z, n1.x, n1.y, n1.z, n2.x, n2.y};
    const unsigned u = __float_as_uint(n2.z);
    #pragma unroll
    for (int i = 0; i < 8; i++) {
        unsigned bits = (__float_as_uint(c[i]) & ~0xFu) | ((u >> (4 * i)) & 0xFu);
        c[i] = __uint_as_float(bits);
    }

    FaceRec r;
    r.a = make_float4(c[0], c[1], c[2], c[3]);
    r.b = make_float4(c[4], c[5], c[6], c[7]);
    g_facerec[f] = r;
}

__global__ __launch_bounds__(256) void normal_shader_kernel(
    const float* __restrict__ bary,             // [N,H,W,K,3]
    const float* __restrict__ dists,            // [N,H,W,K]
    const float* __restrict__ zbuf,             // [N,H,W,K]
    const int*   __restrict__ pix_to_face,      // [N,H,W,K]
    float*       __restrict__ out)              // [N,H,W,3]
{
    __shared__ float so[256 * 3];
    const int tid = threadIdx.x;
    const int p = blockIdx.x * 256 + tid;       // grid covers NPIX exactly

    // ---- coalesced vector loads of per-fragment data ----
    const int4   ptf = __ldg((const int4*)(pix_to_face) + p);
    const float4 dd  = __ldg((const float4*)(dists) + p);
    const float4 zz  = __ldg((const float4*)(zbuf) + p);
    const float4* bb = (const float4*)(bary + (size_t)p * 12);
    const float4 b0 = __ldg(bb + 0);
    const float4 b1 = __ldg(bb + 1);
    const float4 b2 = __ldg(bb + 2);

    int   face[KK] = {ptf.x, ptf.y, ptf.z, ptf.w};
    float dk[KK]   = {dd.x, dd.y, dd.z, dd.w};
    float zk[KK]   = {zz.x, zz.y, zz.z, zz.w};
    float bw[KK][3] = {
        {b0.x, b0.y, b0.z},
        {b0.w, b1.x, b1.y},
        {b1.z, b1.w, b2.x},
        {b2.y, b2.z, b2.w}
    };

    float nrm[KK][3];
    float prob[KK];
    float zinv[KK];
    float zmax = EPSV;

    // Branchless per-fragment pass (invalid fragments ~5e-6 of all — mask
    // multiplies mirror the reference's where(valid, ptf, 0) + masking).
    #pragma unroll
    for (int k = 0; k < KK; k++) {
        const float m = (face[k] >= 0) ? 1.0f : 0.0f;
        const int  fi = max(face[k], 0);

        float4 a, b;
        ldg256(g_facerec + fi, a, b);
        // reconstruct n2z from the 8 stolen nibbles (bit-exact)
        unsigned u =  (fb(a.x) & 0xFu)
                   | ((fb(a.y) & 0xFu) << 4)
                   | ((fb(a.z) & 0xFu) << 8)
                   | ((fb(a.w) & 0xFu) << 12)
                   | ((fb(b.x) & 0xFu) << 16)
                   | ((fb(b.y) & 0xFu) << 20)
                   | ((fb(b.z) & 0xFu) << 24)
                   | ((fb(b.w) & 0xFu) << 28);
        const float n2z = __uint_as_float(u);
        const float w0 = bw[k][0], w1 = bw[k][1], w2 = bw[k][2];
        nrm[k][0] = m * (w0 * a.x + w1 * a.w + w2 * b.z);
        nrm[k][1] = m * (w0 * a.y + w1 * b.x + w2 * b.w);
        nrm[k][2] = m * (w0 * a.z + w1 * b.y + w2 * n2z);

        // sigmoid(-d/SIGMA) * mask  (arg ~N(0,1): __expf err ~1e-6 here)
        prob[k] = m * __fdividef(1.0f, 1.0f + __expf(dk[k] * INV_SG));
        // zi MUST use exact IEEE div: 1 ulp here amplifies ~1e4x in the
        // softmax exponent.
        const float zi = m * ((ZFAR - zk[k]) / (ZFAR - ZNEAR));
        zinv[k] = zi;
        zmax = fmaxf(zmax, zi);
    }

    // ---- softmax blend ----
    float accx = 0.f, accy = 0.f, accz = 0.f, wsum = 0.f;
    #pragma unroll
    for (int k = 0; k < KK; k++) {
        const float w = prob[k] * __expf((zinv[k] - zmax) * INV_SG);
        wsum += w;
        accx += w * nrm[k][0];
        accy += w * nrm[k][1];
        accz += w * nrm[k][2];
    }
    const float delta = fmaxf(__expf((EPSV - zmax) * INV_SG), EPSV);
    const float rdenom = __fdividef(1.0f, wsum + delta);

    // bg = (1,1,1)
    float rx = (accx + delta) * rdenom;
    float ry = (accy + delta) * rdenom;
    float rz = (accz + delta) * rdenom;

    const float n2 = rx * rx + ry * ry + rz * rz;
    const float inv = (n2 > 1e-24f) ? rsqrtf(n2) : 1e12f;
    rx *= inv; ry *= inv; rz *= inv;

    // ---- coalesced store via smem staging (3 STG.128 wavefronts/warp) ----
    so[3 * tid + 0] = rx;
    so[3 * tid + 1] = ry;
    so[3 * tid + 2] = rz;
    __syncthreads();
    if (tid < 192) {
        float4* ob = (float4*)(out + (size_t)blockIdx.x * 768);
        const float4* sp = (const float4*)so;
        ob[tid] = sp[tid];
    }
}

extern "C" void kernel_launch(void* const* d_in, const int* in_sizes, int n_in,
                              void* d_out, int out_size)
{
    // metadata order: verts, vertex_normals, bary_coords, dists, zbuf, faces, pix_to_face
    const float* vertex_normals = (const float*)d_in[1];
    const float* bary           = (const float*)d_in[2];
    const float* dists          = (const float*)d_in[3];
    const float* zbuf           = (const float*)d_in[4];
    const int*   faces          = (const int*)d_in[5];
    const int*   pix_to_face    = (const int*)d_in[6];
    float*       out            = (float*)d_out;

    const int F = in_sizes[5] / 3;   // 200000

    const int threads = 256;
    build_face_records<<<(F + threads - 1) / threads, threads>>>(
        vertex_normals, faces, F);

    normal_shader_kernel<<<NPIX / threads, threads>>>(
        bary, dists, zbuf, pix_to_face, out);
}